// round 1
// baseline (speedup 1.0000x reference)
#include <cuda_runtime.h>

// Problem constants
#define VB 4
#define PP 2048
#define DD 1280
#define HH 16
#define HD 80
#define M_ROWS (VB * PP)     // 8192
#define N_QKV  (3 * DD)      // 3840

// Scratch (static device globals — allocation-guard safe)
__device__ float g_qkv[M_ROWS * N_QKV];     // [8192, 3840]
__device__ float g_q[VB * HH * PP * HD];    // [v][h][p][d]
__device__ float g_k[VB * HH * PP * HD];
__device__ float g_v[VB * HH * PP * HD];
__device__ float g_ao[M_ROWS * DD];         // attention out, [v*p, h*80+d]

// ---------------------------------------------------------------------------
// Tiled SGEMM with bias:  C[M,N] = A[M,K] @ B[K,N] + bias[N]
// BM=BN=128, BK=16, 256 threads, 8x8 per thread.
// All dims here are multiples of the tile sizes (8192/3840/1280).
// ---------------------------------------------------------------------------
#define BM 128
#define BN 128
#define BKK 16

__global__ __launch_bounds__(256) void sgemm_bias(
    const float* __restrict__ A, const float* __restrict__ B,
    const float* __restrict__ bias, float* __restrict__ C,
    int M, int N, int K)
{
    __shared__ float As[BKK][BM + 4];   // transposed A tile, padded
    __shared__ float Bs[BKK][BN];

    const int tid = threadIdx.x;
    const int tx = tid & 15;
    const int ty = tid >> 4;
    const int bm0 = blockIdx.y * BM;
    const int bn0 = blockIdx.x * BN;

    float acc[8][8] = {};

    const float* Aptr = A + (size_t)bm0 * K;
    const float* Bptr = B + bn0;

    for (int k0 = 0; k0 < K; k0 += BKK) {
        // Load A tile 128x16 (512 float4), store transposed
        #pragma unroll
        for (int t = 0; t < 2; t++) {
            int id = tid + t * 256;
            int r  = id >> 2;           // 0..127
            int c4 = (id & 3) * 4;      // 0,4,8,12
            float4 a = *(const float4*)(Aptr + (size_t)r * K + k0 + c4);
            As[c4 + 0][r] = a.x;
            As[c4 + 1][r] = a.y;
            As[c4 + 2][r] = a.z;
            As[c4 + 3][r] = a.w;
        }
        // Load B tile 16x128 (512 float4)
        #pragma unroll
        for (int t = 0; t < 2; t++) {
            int id = tid + t * 256;
            int r  = id >> 5;           // 0..15
            int c4 = (id & 31) * 4;     // 0..124
            *(float4*)&Bs[r][c4] = *(const float4*)(Bptr + (size_t)(k0 + r) * N + c4);
        }
        __syncthreads();

        #pragma unroll
        for (int k = 0; k < BKK; k++) {
            float af[8], bf[8];
            *(float4*)&af[0] = *(const float4*)&As[k][ty * 8];
            *(float4*)&af[4] = *(const float4*)&As[k][ty * 8 + 4];
            *(float4*)&bf[0] = *(const float4*)&Bs[k][tx * 8];
            *(float4*)&bf[4] = *(const float4*)&Bs[k][tx * 8 + 4];
            #pragma unroll
            for (int i = 0; i < 8; i++)
                #pragma unroll
                for (int j = 0; j < 8; j++)
                    acc[i][j] += af[i] * bf[j];
        }
        __syncthreads();
    }

    // Epilogue: add bias, vectorized store
    #pragma unroll
    for (int i = 0; i < 8; i++) {
        size_t row = (size_t)(bm0 + ty * 8 + i);
        #pragma unroll
        for (int j = 0; j < 8; j += 4) {
            int col = bn0 + tx * 8 + j;
            float4 r;
            r.x = acc[i][j + 0] + bias[col + 0];
            r.y = acc[i][j + 1] + bias[col + 1];
            r.z = acc[i][j + 2] + bias[col + 2];
            r.w = acc[i][j + 3] + bias[col + 3];
            *(float4*)(C + row * N + col) = r;
        }
    }
}

// ---------------------------------------------------------------------------
// RoPE + scatter: split g_qkv into Q/K/V in [v][h][p][d] layout; apply rotary
// to Q and K. One thread per (v,p,h,d<40) pair (handles d and d+40).
// rotate_half: rot[d] = -x[d+40] (d<40), rot[d+40] = x[d].
// ---------------------------------------------------------------------------
__global__ __launch_bounds__(256) void rope_scatter(
    const float* __restrict__ qkv, const float* __restrict__ rope)
{
    int idx = blockIdx.x * 256 + threadIdx.x;
    if (idx >= VB * PP * HH * 40) return;
    int d = idx % 40;
    int h = (idx / 40) % HH;
    int p = (idx / (40 * HH)) % PP;
    int v = idx / (40 * HH * PP);

    size_t row = (size_t)v * PP + p;
    const float* qr = qkv + row * N_QKV + h * HD;
    const float* kr = qr + DD;
    const float* vr = qr + 2 * DD;
    const float* rp = rope + row * (2 * HD);

    float c0 = rp[d],      c1 = rp[d + 40];
    float s0 = rp[HD + d], s1 = rp[HD + d + 40];
    float q0 = qr[d], q1 = qr[d + 40];
    float k0 = kr[d], k1 = kr[d + 40];

    size_t ob = ((((size_t)v * HH + h) * PP) + p) * HD;
    g_q[ob + d]      = q0 * c0 - q1 * s0;
    g_q[ob + d + 40] = q1 * c1 + q0 * s1;
    g_k[ob + d]      = k0 * c0 - k1 * s0;
    g_k[ob + d + 40] = k1 * c1 + k0 * s1;
    g_v[ob + d]      = vr[d];
    g_v[ob + d + 40] = vr[d + 40];
}

// ---------------------------------------------------------------------------
// Flash attention: block = (64 q-rows, head h, image v). 256 threads (16x16).
// Keys looped in 64-tiles up to ceil(L/64); masked keys get -1e30 -> exp = 0,
// exactly matching reference's -1e9 mask + softmax (exp underflows to 0).
// ---------------------------------------------------------------------------
#define BQ 64
#define BKV 64
// dynamic smem layout (floats): QsT[80][68] | KsT[80][68] | Vs[64][80] | Ps[64][65]
#define SM_QST 0
#define SM_KST (80 * 68)
#define SM_VS  (2 * 80 * 68)
#define SM_PS  (2 * 80 * 68 + 64 * 80)
#define ATTN_SMEM_FLOATS (2 * 80 * 68 + 64 * 80 + 64 * 65)

__global__ __launch_bounds__(256) void attn_kernel(
    const int* __restrict__ valid_lens)
{
    extern __shared__ float sm[];
    float (*QsT)[68] = (float(*)[68])(sm + SM_QST);
    float (*KsT)[68] = (float(*)[68])(sm + SM_KST);
    float (*Vs)[80]  = (float(*)[80])(sm + SM_VS);
    float (*Ps)[65]  = (float(*)[65])(sm + SM_PS);

    const int tid = threadIdx.x;
    const int tx = tid & 15;
    const int ty = tid >> 4;
    const int q0 = blockIdx.x * BQ;
    const int h = blockIdx.y;
    const int v = blockIdx.z;
    int L = valid_lens[v];
    if (L < 1) L = 1;

    const size_t hb = (((size_t)v * HH + h) * PP) * HD;
    const float* Qh = g_q + hb;
    const float* Kh = g_k + hb;
    const float* Vh = g_v + hb;

    // Load Q tile transposed: QsT[d][r]
    for (int i = tid; i < BQ * 20; i += 256) {
        int r = i / 20, c4 = (i % 20) * 4;
        float4 a = *(const float4*)(Qh + (size_t)(q0 + r) * HD + c4);
        QsT[c4 + 0][r] = a.x;
        QsT[c4 + 1][r] = a.y;
        QsT[c4 + 2][r] = a.z;
        QsT[c4 + 3][r] = a.w;
    }

    float m[4], l[4], o[4][5];
    #pragma unroll
    for (int i = 0; i < 4; i++) {
        m[i] = -1e30f;
        l[i] = 0.f;
        #pragma unroll
        for (int j = 0; j < 5; j++) o[i][j] = 0.f;
    }

    const float scale = 0.111803398874989484f;  // 80^-0.5
    const int nkt = (L + BKV - 1) / BKV;

    for (int kt = 0; kt < nkt; kt++) {
        const int k0 = kt * BKV;
        __syncthreads();  // previous iter's readers of KsT/Vs done
        // Load K tile transposed + V tile
        for (int i = tid; i < BKV * 20; i += 256) {
            int r = i / 20, c4 = (i % 20) * 4;
            float4 a = *(const float4*)(Kh + (size_t)(k0 + r) * HD + c4);
            KsT[c4 + 0][r] = a.x;
            KsT[c4 + 1][r] = a.y;
            KsT[c4 + 2][r] = a.z;
            KsT[c4 + 3][r] = a.w;
            float4 b = *(const float4*)(Vh + (size_t)(k0 + r) * HD + c4);
            *(float4*)&Vs[r][c4] = b;
        }
        __syncthreads();

        // S[4][4] = Q K^T
        float s[4][4] = {};
        #pragma unroll 4
        for (int k = 0; k < HD; k++) {
            float4 qa = *(const float4*)&QsT[k][ty * 4];
            float4 kb = *(const float4*)&KsT[k][tx * 4];
            float qv[4] = {qa.x, qa.y, qa.z, qa.w};
            float kv[4] = {kb.x, kb.y, kb.z, kb.w};
            #pragma unroll
            for (int i = 0; i < 4; i++)
                #pragma unroll
                for (int j = 0; j < 4; j++)
                    s[i][j] += qv[i] * kv[j];
        }

        // scale + key mask
        #pragma unroll
        for (int i = 0; i < 4; i++)
            #pragma unroll
            for (int j = 0; j < 4; j++) {
                s[i][j] *= scale;
                if (k0 + tx * 4 + j >= L) s[i][j] = -1e30f;
            }

        // Online softmax (row reduce across tx = 16 lanes = half warp)
        #pragma unroll
        for (int i = 0; i < 4; i++) {
            float mt = fmaxf(fmaxf(s[i][0], s[i][1]), fmaxf(s[i][2], s[i][3]));
            #pragma unroll
            for (int off = 8; off >= 1; off >>= 1)
                mt = fmaxf(mt, __shfl_xor_sync(0xffffffffu, mt, off));
            float mn = fmaxf(m[i], mt);
            float alpha = __expf(m[i] - mn);
            float rs = 0.f;
            #pragma unroll
            for (int j = 0; j < 4; j++) {
                s[i][j] = __expf(s[i][j] - mn);
                rs += s[i][j];
            }
            #pragma unroll
            for (int off = 8; off >= 1; off >>= 1)
                rs += __shfl_xor_sync(0xffffffffu, rs, off);
            l[i] = l[i] * alpha + rs;
            m[i] = mn;
            #pragma unroll
            for (int j = 0; j < 5; j++) o[i][j] *= alpha;
            #pragma unroll
            for (int j = 0; j < 4; j++) Ps[ty * 4 + i][tx * 4 + j] = s[i][j];
        }
        __syncthreads();

        // O += P @ V  (each thread: 4 rows x 5 head-dims)
        #pragma unroll 2
        for (int c = 0; c < BKV; c++) {
            float pv[4];
            #pragma unroll
            for (int i = 0; i < 4; i++) pv[i] = Ps[ty * 4 + i][c];
            #pragma unroll
            for (int j = 0; j < 5; j++) {
                float vv = Vs[c][tx * 5 + j];
                #pragma unroll
                for (int i = 0; i < 4; i++) o[i][j] += pv[i] * vv;
            }
        }
    }

    // Normalize + write AO in [v*p, h*80+d] layout
    #pragma unroll
    for (int i = 0; i < 4; i++) {
        float inv = 1.f / l[i];
        int r = q0 + ty * 4 + i;
        size_t orow = ((size_t)v * PP + r) * DD + h * HD;
        #pragma unroll
        for (int j = 0; j < 5; j++)
            g_ao[orow + tx * 5 + j] = o[i][j] * inv;
    }
}

// ---------------------------------------------------------------------------
// Launch
// ---------------------------------------------------------------------------
extern "C" void kernel_launch(void* const* d_in, const int* in_sizes, int n_in,
                              void* d_out, int out_size)
{
    const float* hs    = (const float*)d_in[0];
    const float* rope  = (const float*)d_in[1];
    const int*   vlens = (const int*)d_in[2];
    const float* wqkv  = (const float*)d_in[3];
    const float* bqkv  = (const float*)d_in[4];
    const float* wproj = (const float*)d_in[5];
    const float* bproj = (const float*)d_in[6];
    float* out = (float*)d_out;

    float *p_qkv, *p_ao;
    cudaGetSymbolAddress((void**)&p_qkv, g_qkv);
    cudaGetSymbolAddress((void**)&p_ao,  g_ao);

    // 1) QKV GEMM: [8192,1280] @ [1280,3840] + bias
    sgemm_bias<<<dim3(N_QKV / BN, M_ROWS / BM), 256>>>(
        hs, wqkv, bqkv, p_qkv, M_ROWS, N_QKV, DD);

    // 2) RoPE + scatter into per-head Q/K/V
    {
        int total = VB * PP * HH * 40;
        rope_scatter<<<(total + 255) / 256, 256>>>(p_qkv, rope);
    }

    // 3) Flash attention
    {
        int smem_bytes = ATTN_SMEM_FLOATS * (int)sizeof(float);
        cudaFuncSetAttribute(attn_kernel,
                             cudaFuncAttributeMaxDynamicSharedMemorySize,
                             smem_bytes);
        attn_kernel<<<dim3(PP / BQ, HH, VB), 256, smem_bytes>>>(vlens);
    }

    // 4) Output projection: [8192,1280] @ [1280,1280] + bias
    sgemm_bias<<<dim3(DD / BN, M_ROWS / BM), 256>>>(
        p_ao, wproj, bproj, out, M_ROWS, DD, DD);
}

// round 4
// speedup vs baseline: 1.6232x; 1.6232x over previous
#include <cuda_runtime.h>
#include <cuda_bf16.h>
#include <cstdint>

// Problem constants
#define VB 4
#define PP 2048
#define DD 1280
#define HH 16
#define HD 80
#define M_ROWS (VB * PP)     // 8192
#define N_QKV  (3 * DD)      // 3840

// ---------------------------------------------------------------------------
// Scratch (static device globals — allocation-guard safe)
// ---------------------------------------------------------------------------
__device__ float g_qkv[M_ROWS * N_QKV];               // [8192, 3840] fp32
__device__ float g_q[VB * HH * PP * HD];              // [v][h][p][d]
__device__ float g_k[VB * HH * PP * HD];
__device__ float g_v[VB * HH * PP * HD];
__device__ float g_ao[M_ROWS * DD];                   // attention out
__device__ __nv_bfloat16 g_ahi[M_ROWS * DD];          // split A (hs, then ao)
__device__ __nv_bfloat16 g_alo[M_ROWS * DD];
__device__ __nv_bfloat16 g_bhi[N_QKV * DD];           // split W^T [N,K]
__device__ __nv_bfloat16 g_blo[N_QKV * DD];

// ---------------------------------------------------------------------------
// Helpers
// ---------------------------------------------------------------------------
__device__ __forceinline__ uint32_t smem_u32(const void* p) {
    uint32_t a;
    asm("{ .reg .u64 t; cvta.to.shared.u64 t, %1; cvt.u32.u64 %0, t; }" : "=r"(a) : "l"(p));
    return a;
}

#define CP_ASYNC16(dst, src) \
    asm volatile("cp.async.cg.shared.global [%0], [%1], 16;" :: "r"(dst), "l"(src))
#define CP_COMMIT() asm volatile("cp.async.commit_group;" ::: "memory")
#define CP_WAIT(n)  asm volatile("cp.async.wait_group %0;" :: "n"(n) : "memory")

__device__ __forceinline__ void ldsm_x4(uint32_t& r0, uint32_t& r1, uint32_t& r2, uint32_t& r3,
                                        uint32_t addr) {
    asm volatile("ldmatrix.sync.aligned.m8n8.x4.shared.b16 {%0,%1,%2,%3}, [%4];"
                 : "=r"(r0), "=r"(r1), "=r"(r2), "=r"(r3) : "r"(addr));
}
__device__ __forceinline__ void ldsm_x2(uint32_t& r0, uint32_t& r1, uint32_t addr) {
    asm volatile("ldmatrix.sync.aligned.m8n8.x2.shared.b16 {%0,%1}, [%2];"
                 : "=r"(r0), "=r"(r1) : "r"(addr));
}
__device__ __forceinline__ void mma16816(float* c, const uint32_t* a, const uint32_t* b) {
    asm volatile("mma.sync.aligned.m16n8k16.row.col.f32.bf16.bf16.f32 "
                 "{%0,%1,%2,%3}, {%4,%5,%6,%7}, {%8,%9}, {%0,%1,%2,%3};"
                 : "+f"(c[0]), "+f"(c[1]), "+f"(c[2]), "+f"(c[3])
                 : "r"(a[0]), "r"(a[1]), "r"(a[2]), "r"(a[3]), "r"(b[0]), "r"(b[1]));
}

__device__ __forceinline__ uint32_t swz(uint32_t x) { return x ^ ((x >> 3) & 0x70u); }

// ---------------------------------------------------------------------------
// Split fp32 -> hi/lo bf16
// ---------------------------------------------------------------------------
__global__ __launch_bounds__(256) void split_kernel(
    const float* __restrict__ x, __nv_bfloat16* __restrict__ hi,
    __nv_bfloat16* __restrict__ lo, int n)
{
    int i = (blockIdx.x * 256 + threadIdx.x) * 4;
    if (i >= n) return;
    float4 v = *(const float4*)(x + i);
    __nv_bfloat16 h0 = __float2bfloat16(v.x);
    __nv_bfloat16 h1 = __float2bfloat16(v.y);
    __nv_bfloat16 h2 = __float2bfloat16(v.z);
    __nv_bfloat16 h3 = __float2bfloat16(v.w);
    ((__nv_bfloat162*)(hi + i))[0] = __nv_bfloat162(h0, h1);
    ((__nv_bfloat162*)(hi + i))[1] = __nv_bfloat162(h2, h3);
    __nv_bfloat16 l0 = __float2bfloat16(v.x - __bfloat162float(h0));
    __nv_bfloat16 l1 = __float2bfloat16(v.y - __bfloat162float(h1));
    __nv_bfloat16 l2 = __float2bfloat16(v.z - __bfloat162float(h2));
    __nv_bfloat16 l3 = __float2bfloat16(v.w - __bfloat162float(h3));
    ((__nv_bfloat162*)(lo + i))[0] = __nv_bfloat162(l0, l1);
    ((__nv_bfloat162*)(lo + i))[1] = __nv_bfloat162(l2, l3);
}

// ---------------------------------------------------------------------------
// Transpose + split: w [K,N] fp32 -> thi/tlo [N,K] bf16
// ---------------------------------------------------------------------------
__global__ __launch_bounds__(256) void transpose_split(
    const float* __restrict__ w, __nv_bfloat16* __restrict__ thi,
    __nv_bfloat16* __restrict__ tlo, int K, int N)
{
    __shared__ float t[32][33];
    int n0 = blockIdx.x * 32, k0 = blockIdx.y * 32;
    int tx = threadIdx.x & 31, ty = threadIdx.x >> 5;
    #pragma unroll
    for (int r = ty; r < 32; r += 8)
        t[r][tx] = w[(size_t)(k0 + r) * N + n0 + tx];
    __syncthreads();
    #pragma unroll
    for (int r = ty; r < 32; r += 8) {
        float v = t[tx][r];
        __nv_bfloat16 h = __float2bfloat16(v);
        size_t o = (size_t)(n0 + r) * K + k0 + tx;
        thi[o] = h;
        tlo[o] = __float2bfloat16(v - __bfloat162float(h));
    }
}

// ---------------------------------------------------------------------------
// mma.sync split-bf16 GEMM: C[M,N] = A[M,K] @ B^T[N,K] + bias
// CTA 128x128, K-chunk 64, 8 warps (2M x 4N), warp tile 64x32,
// double-buffered cp.async with SW128 swizzle, ldmatrix fragments.
// ---------------------------------------------------------------------------
#define GTM 128
#define GTN 128
#define GKC 64
#define MAT_B 16384u             // 128 rows * 128 bytes per matrix tile
#define STAGE_B (4u * MAT_B)     // Ahi | Alo | Bhi | Blo
#define GEMM_SMEM (2 * STAGE_B)  // 131072 bytes

__device__ __forceinline__ void load_chunk4(
    uint32_t sb, int buf,
    const __nv_bfloat16* a0, const __nv_bfloat16* a1,
    const __nv_bfloat16* b0, const __nv_bfloat16* b1,
    int k0, int tid, int K)
{
    const __nv_bfloat16* srcs[4] = {a0 + k0, a1 + k0, b0 + k0, b1 + k0};
    uint32_t stage = sb + (uint32_t)buf * STAGE_B;
    #pragma unroll
    for (int mat = 0; mat < 4; mat++) {
        uint32_t tbase = stage + (uint32_t)mat * MAT_B;
        const __nv_bfloat16* s = srcs[mat];
        #pragma unroll
        for (int i = 0; i < 4; i++) {
            int g = tid + i * 256;          // granule 0..1023
            int row = g >> 3;
            int c16 = g & 7;
            uint32_t boff = (uint32_t)(row * 128 + c16 * 16);
            CP_ASYNC16(tbase + swz(boff), s + (size_t)row * K + c16 * 8);
        }
    }
}

__global__ __launch_bounds__(256) void gemm_mma_bf16x3(
    const __nv_bfloat16* __restrict__ Ahi, const __nv_bfloat16* __restrict__ Alo,
    const __nv_bfloat16* __restrict__ Bhi, const __nv_bfloat16* __restrict__ Blo,
    const float* __restrict__ bias, float* __restrict__ C, int K, int N)
{
    extern __shared__ char smem[];
    uint32_t sb = smem_u32(smem);
    const int tid = threadIdx.x;
    const int lane = tid & 31;
    const int wid = tid >> 5;
    const int wm = wid >> 2;        // 0..1  (64-row slab)
    const int wn = wid & 3;         // 0..3  (32-col slab)
    const int m0 = blockIdx.y * GTM;
    const int n0 = blockIdx.x * GTN;

    const __nv_bfloat16* a0 = Ahi + (size_t)m0 * K;
    const __nv_bfloat16* a1 = Alo + (size_t)m0 * K;
    const __nv_bfloat16* b0 = Bhi + (size_t)n0 * K;
    const __nv_bfloat16* b1 = Blo + (size_t)n0 * K;

    float acc[4][4][4];
    #pragma unroll
    for (int i = 0; i < 4; i++)
        #pragma unroll
        for (int j = 0; j < 4; j++)
            #pragma unroll
            for (int t = 0; t < 4; t++) acc[i][j][t] = 0.f;

    // Per-lane ldmatrix address components (byte offsets within a 128B-row tile)
    // A x4: sub = lane>>3 (0..3): row = (lane&7) + (sub&1)*8, col16 = sub>>1
    const int a_row_l = (lane & 7) + ((lane >> 3) & 1) * 8;
    const int a_c16_l = (lane >> 4);
    // B x2: sub = (lane>>3)&1 : row = lane&7, col16 = sub
    const int b_row_l = (lane & 7);
    const int b_c16_l = ((lane >> 3) & 1);

    const int nch = K / GKC;

    load_chunk4(sb, 0, a0, a1, b0, b1, 0, tid, K);
    CP_COMMIT();

    for (int it = 0; it < nch; it++) {
        const int b = it & 1;
        if (it + 1 < nch) {
            load_chunk4(sb, b ^ 1, a0, a1, b0, b1, (it + 1) * GKC, tid, K);
            CP_COMMIT();
            CP_WAIT(1);
        } else {
            CP_WAIT(0);
        }
        __syncthreads();

        uint32_t stage = sb + (uint32_t)b * STAGE_B;
        uint32_t sAhi = stage;
        uint32_t sAlo = stage + MAT_B;
        uint32_t sBhi = stage + 2 * MAT_B;
        uint32_t sBlo = stage + 3 * MAT_B;

        #pragma unroll
        for (int ks = 0; ks < 4; ks++) {   // 4 x k16 per 64-chunk
            uint32_t ahi[4][4], alo[4][4], bhi[4][2], blo[4][2];
            #pragma unroll
            for (int mt = 0; mt < 4; mt++) {
                uint32_t boff = (uint32_t)((wm * 64 + mt * 16 + a_row_l) * 128 +
                                           (ks * 2 + a_c16_l) * 16);
                uint32_t so = swz(boff);
                ldsm_x4(ahi[mt][0], ahi[mt][1], ahi[mt][2], ahi[mt][3], sAhi + so);
                ldsm_x4(alo[mt][0], alo[mt][1], alo[mt][2], alo[mt][3], sAlo + so);
            }
            #pragma unroll
            for (int nt = 0; nt < 4; nt++) {
                uint32_t boff = (uint32_t)((wn * 32 + nt * 8 + b_row_l) * 128 +
                                           (ks * 2 + b_c16_l) * 16);
                uint32_t so = swz(boff);
                ldsm_x2(bhi[nt][0], bhi[nt][1], sBhi + so);
                ldsm_x2(blo[nt][0], blo[nt][1], sBlo + so);
            }
            #pragma unroll
            for (int mt = 0; mt < 4; mt++)
                #pragma unroll
                for (int nt = 0; nt < 4; nt++) {
                    mma16816(acc[mt][nt], ahi[mt], bhi[nt]);
                    mma16816(acc[mt][nt], ahi[mt], blo[nt]);
                    mma16816(acc[mt][nt], alo[mt], bhi[nt]);
                }
        }
        __syncthreads();
    }

    // Epilogue: c0,c1 -> (row = lane/4, col = 2*(lane%4)), c2,c3 -> row+8
    const int r_base = m0 + wm * 64 + (lane >> 2);
    const int c_base = n0 + wn * 32 + (lane & 3) * 2;
    #pragma unroll
    for (int mt = 0; mt < 4; mt++) {
        #pragma unroll
        for (int nt = 0; nt < 4; nt++) {
            int col = c_base + nt * 8;
            float bx = bias[col], by = bias[col + 1];
            int r0 = r_base + mt * 16;
            float2 v0 = {acc[mt][nt][0] + bx, acc[mt][nt][1] + by};
            float2 v1 = {acc[mt][nt][2] + bx, acc[mt][nt][3] + by};
            *(float2*)(C + (size_t)r0 * N + col) = v0;
            *(float2*)(C + (size_t)(r0 + 8) * N + col) = v1;
        }
    }
}

// ---------------------------------------------------------------------------
// RoPE + scatter (unchanged)
// ---------------------------------------------------------------------------
__global__ __launch_bounds__(256) void rope_scatter(
    const float* __restrict__ qkv, const float* __restrict__ rope)
{
    int idx = blockIdx.x * 256 + threadIdx.x;
    if (idx >= VB * PP * HH * 40) return;
    int d = idx % 40;
    int h = (idx / 40) % HH;
    int p = (idx / (40 * HH)) % PP;
    int v = idx / (40 * HH * PP);

    size_t row = (size_t)v * PP + p;
    const float* qr = qkv + row * N_QKV + h * HD;
    const float* kr = qr + DD;
    const float* vr = qr + 2 * DD;
    const float* rp = rope + row * (2 * HD);

    float c0 = rp[d],      c1 = rp[d + 40];
    float s0 = rp[HD + d], s1 = rp[HD + d + 40];
    float q0 = qr[d], q1 = qr[d + 40];
    float k0 = kr[d], k1 = kr[d + 40];

    size_t ob = ((((size_t)v * HH + h) * PP) + p) * HD;
    g_q[ob + d]      = q0 * c0 - q1 * s0;
    g_q[ob + d + 40] = q1 * c1 + q0 * s1;
    g_k[ob + d]      = k0 * c0 - k1 * s0;
    g_k[ob + d + 40] = k1 * c1 + k0 * s1;
    g_v[ob + d]      = vr[d];
    g_v[ob + d + 40] = vr[d + 40];
}

// ---------------------------------------------------------------------------
// Flash attention (unchanged)
// ---------------------------------------------------------------------------
#define BQ 64
#define BKV 64
#define SM_QST 0
#define SM_KST (80 * 68)
#define SM_VS  (2 * 80 * 68)
#define SM_PS  (2 * 80 * 68 + 64 * 80)
#define ATTN_SMEM_FLOATS (2 * 80 * 68 + 64 * 80 + 64 * 65)

__global__ __launch_bounds__(256) void attn_kernel(
    const int* __restrict__ valid_lens)
{
    extern __shared__ float sm[];
    float (*QsT)[68] = (float(*)[68])(sm + SM_QST);
    float (*KsT)[68] = (float(*)[68])(sm + SM_KST);
    float (*Vs)[80]  = (float(*)[80])(sm + SM_VS);
    float (*Ps)[65]  = (float(*)[65])(sm + SM_PS);

    const int tid = threadIdx.x;
    const int tx = tid & 15;
    const int ty = tid >> 4;
    const int q0 = blockIdx.x * BQ;
    const int h = blockIdx.y;
    const int v = blockIdx.z;
    int L = valid_lens[v];
    if (L < 1) L = 1;

    const size_t hb = (((size_t)v * HH + h) * PP) * HD;
    const float* Qh = g_q + hb;
    const float* Kh = g_k + hb;
    const float* Vh = g_v + hb;

    for (int i = tid; i < BQ * 20; i += 256) {
        int r = i / 20, c4 = (i % 20) * 4;
        float4 a = *(const float4*)(Qh + (size_t)(q0 + r) * HD + c4);
        QsT[c4 + 0][r] = a.x;
        QsT[c4 + 1][r] = a.y;
        QsT[c4 + 2][r] = a.z;
        QsT[c4 + 3][r] = a.w;
    }

    float m[4], l[4], o[4][5];
    #pragma unroll
    for (int i = 0; i < 4; i++) {
        m[i] = -1e30f;
        l[i] = 0.f;
        #pragma unroll
        for (int j = 0; j < 5; j++) o[i][j] = 0.f;
    }

    const float scale = 0.111803398874989484f;
    const int nkt = (L + BKV - 1) / BKV;

    for (int kt = 0; kt < nkt; kt++) {
        const int k0 = kt * BKV;
        __syncthreads();
        for (int i = tid; i < BKV * 20; i += 256) {
            int r = i / 20, c4 = (i % 20) * 4;
            float4 a = *(const float4*)(Kh + (size_t)(k0 + r) * HD + c4);
            KsT[c4 + 0][r] = a.x;
            KsT[c4 + 1][r] = a.y;
            KsT[c4 + 2][r] = a.z;
            KsT[c4 + 3][r] = a.w;
            float4 b = *(const float4*)(Vh + (size_t)(k0 + r) * HD + c4);
            *(float4*)&Vs[r][c4] = b;
        }
        __syncthreads();

        float s[4][4] = {};
        #pragma unroll 4
        for (int k = 0; k < HD; k++) {
            float4 qa = *(const float4*)&QsT[k][ty * 4];
            float4 kb = *(const float4*)&KsT[k][tx * 4];
            float qv[4] = {qa.x, qa.y, qa.z, qa.w};
            float kv[4] = {kb.x, kb.y, kb.z, kb.w};
            #pragma unroll
            for (int i = 0; i < 4; i++)
                #pragma unroll
                for (int j = 0; j < 4; j++)
                    s[i][j] += qv[i] * kv[j];
        }

        #pragma unroll
        for (int i = 0; i < 4; i++)
            #pragma unroll
            for (int j = 0; j < 4; j++) {
                s[i][j] *= scale;
                if (k0 + tx * 4 + j >= L) s[i][j] = -1e30f;
            }

        #pragma unroll
        for (int i = 0; i < 4; i++) {
            float mt = fmaxf(fmaxf(s[i][0], s[i][1]), fmaxf(s[i][2], s[i][3]));
            #pragma unroll
            for (int off = 8; off >= 1; off >>= 1)
                mt = fmaxf(mt, __shfl_xor_sync(0xffffffffu, mt, off));
            float mn = fmaxf(m[i], mt);
            float alpha = __expf(m[i] - mn);
            float rs = 0.f;
            #pragma unroll
            for (int j = 0; j < 4; j++) {
                s[i][j] = __expf(s[i][j] - mn);
                rs += s[i][j];
            }
            #pragma unroll
            for (int off = 8; off >= 1; off >>= 1)
                rs += __shfl_xor_sync(0xffffffffu, rs, off);
            l[i] = l[i] * alpha + rs;
            m[i] = mn;
            #pragma unroll
            for (int j = 0; j < 5; j++) o[i][j] *= alpha;
            #pragma unroll
            for (int j = 0; j < 4; j++) Ps[ty * 4 + i][tx * 4 + j] = s[i][j];
        }
        __syncthreads();

        #pragma unroll 2
        for (int c = 0; c < BKV; c++) {
            float pv[4];
            #pragma unroll
            for (int i = 0; i < 4; i++) pv[i] = Ps[ty * 4 + i][c];
            #pragma unroll
            for (int j = 0; j < 5; j++) {
                float vv = Vs[c][tx * 5 + j];
                #pragma unroll
                for (int i = 0; i < 4; i++) o[i][j] += pv[i] * vv;
            }
        }
    }

    #pragma unroll
    for (int i = 0; i < 4; i++) {
        float inv = 1.f / l[i];
        int r = q0 + ty * 4 + i;
        size_t orow = ((size_t)v * PP + r) * DD + h * HD;
        #pragma unroll
        for (int j = 0; j < 5; j++)
            g_ao[orow + tx * 5 + j] = o[i][j] * inv;
    }
}

// ---------------------------------------------------------------------------
// Launch
// ---------------------------------------------------------------------------
extern "C" void kernel_launch(void* const* d_in, const int* in_sizes, int n_in,
                              void* d_out, int out_size)
{
    const float* hs    = (const float*)d_in[0];
    const float* rope  = (const float*)d_in[1];
    const int*   vlens = (const int*)d_in[2];
    const float* wqkv  = (const float*)d_in[3];
    const float* bqkv  = (const float*)d_in[4];
    const float* wproj = (const float*)d_in[5];
    const float* bproj = (const float*)d_in[6];
    float* out = (float*)d_out;

    float *p_qkv, *p_ao;
    __nv_bfloat16 *p_ahi, *p_alo, *p_bhi, *p_blo;
    cudaGetSymbolAddress((void**)&p_qkv, g_qkv);
    cudaGetSymbolAddress((void**)&p_ao,  g_ao);
    cudaGetSymbolAddress((void**)&p_ahi, g_ahi);
    cudaGetSymbolAddress((void**)&p_alo, g_alo);
    cudaGetSymbolAddress((void**)&p_bhi, g_bhi);
    cudaGetSymbolAddress((void**)&p_blo, g_blo);

    cudaFuncSetAttribute(gemm_mma_bf16x3,
                         cudaFuncAttributeMaxDynamicSharedMemorySize, GEMM_SMEM);

    // 1) Split hidden states, transpose+split W_qkv
    {
        int n = M_ROWS * DD;
        split_kernel<<<(n / 4 + 255) / 256, 256>>>(hs, p_ahi, p_alo, n);
        transpose_split<<<dim3(N_QKV / 32, DD / 32), 256>>>(wqkv, p_bhi, p_blo, DD, N_QKV);
    }

    // 2) QKV GEMM (mma.sync split-bf16): [8192,1280] @ [1280,3840] + bias
    gemm_mma_bf16x3<<<dim3(N_QKV / GTN, M_ROWS / GTM), 256, GEMM_SMEM>>>(
        p_ahi, p_alo, p_bhi, p_blo, bqkv, p_qkv, DD, N_QKV);

    // 3) RoPE + scatter
    {
        int total = VB * PP * HH * 40;
        rope_scatter<<<(total + 255) / 256, 256>>>(p_qkv, rope);
    }

    // 4) Flash attention
    {
        int smem_bytes = ATTN_SMEM_FLOATS * (int)sizeof(float);
        cudaFuncSetAttribute(attn_kernel,
                             cudaFuncAttributeMaxDynamicSharedMemorySize, smem_bytes);
        attn_kernel<<<dim3(PP / BQ, HH, VB), 256, smem_bytes>>>(vlens);
    }

    // 5) Split attention output, transpose+split W_proj
    {
        int n = M_ROWS * DD;
        split_kernel<<<(n / 4 + 255) / 256, 256>>>(p_ao, p_ahi, p_alo, n);
        transpose_split<<<dim3(DD / 32, DD / 32), 256>>>(wproj, p_bhi, p_blo, DD, DD);
    }

    // 6) Output projection (mma.sync): [8192,1280] @ [1280,1280] + bias
    gemm_mma_bf16x3<<<dim3(DD / GTN, M_ROWS / GTM), 256, GEMM_SMEM>>>(
        p_ahi, p_alo, p_bhi, p_blo, bproj, out, DD, DD);
}

// round 5
// speedup vs baseline: 3.4413x; 2.1201x over previous
#include <cuda_runtime.h>
#include <cuda_bf16.h>
#include <cuda_fp16.h>
#include <cstdint>

// Problem constants
#define VB 4
#define PP 2048
#define DD 1280
#define HH 16
#define HD 80
#define M_ROWS (VB * PP)     // 8192
#define N_QKV  (3 * DD)      // 3840
#define QK_SCALE 0.111803398874989484f

// ---------------------------------------------------------------------------
// Scratch (static device globals — allocation-guard safe)
// ---------------------------------------------------------------------------
__device__ float g_qkv[M_ROWS * N_QKV];               // [8192, 3840] fp32
__device__ float g_ao[M_ROWS * DD];                   // attention out
__device__ __nv_bfloat16 g_ahi[M_ROWS * DD];          // split A (hs, then ao)
__device__ __nv_bfloat16 g_alo[M_ROWS * DD];
__device__ __nv_bfloat16 g_bhi[N_QKV * DD];           // split W^T [N,K]
__device__ __nv_bfloat16 g_blo[N_QKV * DD];
// fp16 attention operands
__device__ __align__(16) __half g_qhi2[VB * HH * PP * HD];  // [v][h][p][d], scaled
__device__ __align__(16) __half g_qlo2[VB * HH * PP * HD];
__device__ __align__(16) __half g_khi2[VB * HH * PP * HD];
__device__ __align__(16) __half g_klo2[VB * HH * PP * HD];
__device__ __align__(16) __half g_vt[VB * HH * HD * PP];    // [v][h][d][p]

// ---------------------------------------------------------------------------
// Helpers
// ---------------------------------------------------------------------------
__device__ __forceinline__ uint32_t smem_u32(const void* p) {
    uint32_t a;
    asm("{ .reg .u64 t; cvta.to.shared.u64 t, %1; cvt.u32.u64 %0, t; }" : "=r"(a) : "l"(p));
    return a;
}

#define CP_ASYNC16(dst, src) \
    asm volatile("cp.async.cg.shared.global [%0], [%1], 16;" :: "r"(dst), "l"(src))
#define CP_COMMIT() asm volatile("cp.async.commit_group;" ::: "memory")
#define CP_WAIT(n)  asm volatile("cp.async.wait_group %0;" :: "n"(n) : "memory")

__device__ __forceinline__ void ldsm_x4(uint32_t& r0, uint32_t& r1, uint32_t& r2, uint32_t& r3,
                                        uint32_t addr) {
    asm volatile("ldmatrix.sync.aligned.m8n8.x4.shared.b16 {%0,%1,%2,%3}, [%4];"
                 : "=r"(r0), "=r"(r1), "=r"(r2), "=r"(r3) : "r"(addr));
}
__device__ __forceinline__ void ldsm_x2(uint32_t& r0, uint32_t& r1, uint32_t addr) {
    asm volatile("ldmatrix.sync.aligned.m8n8.x2.shared.b16 {%0,%1}, [%2];"
                 : "=r"(r0), "=r"(r1) : "r"(addr));
}
__device__ __forceinline__ void mma16816bf(float* c, const uint32_t* a, const uint32_t* b) {
    asm volatile("mma.sync.aligned.m16n8k16.row.col.f32.bf16.bf16.f32 "
                 "{%0,%1,%2,%3}, {%4,%5,%6,%7}, {%8,%9}, {%0,%1,%2,%3};"
                 : "+f"(c[0]), "+f"(c[1]), "+f"(c[2]), "+f"(c[3])
                 : "r"(a[0]), "r"(a[1]), "r"(a[2]), "r"(a[3]), "r"(b[0]), "r"(b[1]));
}
__device__ __forceinline__ void mma16816h(float* c, const uint32_t* a, const uint32_t* b) {
    asm volatile("mma.sync.aligned.m16n8k16.row.col.f32.f16.f16.f32 "
                 "{%0,%1,%2,%3}, {%4,%5,%6,%7}, {%8,%9}, {%0,%1,%2,%3};"
                 : "+f"(c[0]), "+f"(c[1]), "+f"(c[2]), "+f"(c[3])
                 : "r"(a[0]), "r"(a[1]), "r"(a[2]), "r"(a[3]), "r"(b[0]), "r"(b[1]));
}

__device__ __forceinline__ uint32_t swz(uint32_t x) { return x ^ ((x >> 3) & 0x70u); }

// ---------------------------------------------------------------------------
// Split fp32 -> hi/lo bf16
// ---------------------------------------------------------------------------
__global__ __launch_bounds__(256) void split_kernel(
    const float* __restrict__ x, __nv_bfloat16* __restrict__ hi,
    __nv_bfloat16* __restrict__ lo, int n)
{
    int i = (blockIdx.x * 256 + threadIdx.x) * 4;
    if (i >= n) return;
    float4 v = *(const float4*)(x + i);
    __nv_bfloat16 h0 = __float2bfloat16(v.x);
    __nv_bfloat16 h1 = __float2bfloat16(v.y);
    __nv_bfloat16 h2 = __float2bfloat16(v.z);
    __nv_bfloat16 h3 = __float2bfloat16(v.w);
    ((__nv_bfloat162*)(hi + i))[0] = __nv_bfloat162(h0, h1);
    ((__nv_bfloat162*)(hi + i))[1] = __nv_bfloat162(h2, h3);
    __nv_bfloat16 l0 = __float2bfloat16(v.x - __bfloat162float(h0));
    __nv_bfloat16 l1 = __float2bfloat16(v.y - __bfloat162float(h1));
    __nv_bfloat16 l2 = __float2bfloat16(v.z - __bfloat162float(h2));
    __nv_bfloat16 l3 = __float2bfloat16(v.w - __bfloat162float(h3));
    ((__nv_bfloat162*)(lo + i))[0] = __nv_bfloat162(l0, l1);
    ((__nv_bfloat162*)(lo + i))[1] = __nv_bfloat162(l2, l3);
}

// ---------------------------------------------------------------------------
// Transpose + split: w [K,N] fp32 -> thi/tlo [N,K] bf16
// ---------------------------------------------------------------------------
__global__ __launch_bounds__(256) void transpose_split(
    const float* __restrict__ w, __nv_bfloat16* __restrict__ thi,
    __nv_bfloat16* __restrict__ tlo, int K, int N)
{
    __shared__ float t[32][33];
    int n0 = blockIdx.x * 32, k0 = blockIdx.y * 32;
    int tx = threadIdx.x & 31, ty = threadIdx.x >> 5;
    #pragma unroll
    for (int r = ty; r < 32; r += 8)
        t[r][tx] = w[(size_t)(k0 + r) * N + n0 + tx];
    __syncthreads();
    #pragma unroll
    for (int r = ty; r < 32; r += 8) {
        float v = t[tx][r];
        __nv_bfloat16 h = __float2bfloat16(v);
        size_t o = (size_t)(n0 + r) * K + k0 + tx;
        thi[o] = h;
        tlo[o] = __float2bfloat16(v - __bfloat162float(h));
    }
}

// ---------------------------------------------------------------------------
// mma.sync split-bf16 GEMM (unchanged, known-good)
// ---------------------------------------------------------------------------
#define GTM 128
#define GTN 128
#define GKC 64
#define MAT_B 16384u
#define STAGE_B (4u * MAT_B)
#define GEMM_SMEM (2 * STAGE_B)

__device__ __forceinline__ void load_chunk4(
    uint32_t sb, int buf,
    const __nv_bfloat16* a0, const __nv_bfloat16* a1,
    const __nv_bfloat16* b0, const __nv_bfloat16* b1,
    int k0, int tid, int K)
{
    const __nv_bfloat16* srcs[4] = {a0 + k0, a1 + k0, b0 + k0, b1 + k0};
    uint32_t stage = sb + (uint32_t)buf * STAGE_B;
    #pragma unroll
    for (int mat = 0; mat < 4; mat++) {
        uint32_t tbase = stage + (uint32_t)mat * MAT_B;
        const __nv_bfloat16* s = srcs[mat];
        #pragma unroll
        for (int i = 0; i < 4; i++) {
            int g = tid + i * 256;
            int row = g >> 3;
            int c16 = g & 7;
            uint32_t boff = (uint32_t)(row * 128 + c16 * 16);
            CP_ASYNC16(tbase + swz(boff), s + (size_t)row * K + c16 * 8);
        }
    }
}

__global__ __launch_bounds__(256) void gemm_mma_bf16x3(
    const __nv_bfloat16* __restrict__ Ahi, const __nv_bfloat16* __restrict__ Alo,
    const __nv_bfloat16* __restrict__ Bhi, const __nv_bfloat16* __restrict__ Blo,
    const float* __restrict__ bias, float* __restrict__ C, int K, int N)
{
    extern __shared__ char smem[];
    uint32_t sb = smem_u32(smem);
    const int tid = threadIdx.x;
    const int lane = tid & 31;
    const int wid = tid >> 5;
    const int wm = wid >> 2;
    const int wn = wid & 3;
    const int m0 = blockIdx.y * GTM;
    const int n0 = blockIdx.x * GTN;

    const __nv_bfloat16* a0 = Ahi + (size_t)m0 * K;
    const __nv_bfloat16* a1 = Alo + (size_t)m0 * K;
    const __nv_bfloat16* b0 = Bhi + (size_t)n0 * K;
    const __nv_bfloat16* b1 = Blo + (size_t)n0 * K;

    float acc[4][4][4];
    #pragma unroll
    for (int i = 0; i < 4; i++)
        #pragma unroll
        for (int j = 0; j < 4; j++)
            #pragma unroll
            for (int t = 0; t < 4; t++) acc[i][j][t] = 0.f;

    const int a_row_l = (lane & 7) + ((lane >> 3) & 1) * 8;
    const int a_c16_l = (lane >> 4);
    const int b_row_l = (lane & 7);
    const int b_c16_l = ((lane >> 3) & 1);

    const int nch = K / GKC;

    load_chunk4(sb, 0, a0, a1, b0, b1, 0, tid, K);
    CP_COMMIT();

    for (int it = 0; it < nch; it++) {
        const int b = it & 1;
        if (it + 1 < nch) {
            load_chunk4(sb, b ^ 1, a0, a1, b0, b1, (it + 1) * GKC, tid, K);
            CP_COMMIT();
            CP_WAIT(1);
        } else {
            CP_WAIT(0);
        }
        __syncthreads();

        uint32_t stage = sb + (uint32_t)b * STAGE_B;
        uint32_t sAhi = stage;
        uint32_t sAlo = stage + MAT_B;
        uint32_t sBhi = stage + 2 * MAT_B;
        uint32_t sBlo = stage + 3 * MAT_B;

        #pragma unroll
        for (int ks = 0; ks < 4; ks++) {
            uint32_t ahi[4][4], alo[4][4], bhi[4][2], blo[4][2];
            #pragma unroll
            for (int mt = 0; mt < 4; mt++) {
                uint32_t boff = (uint32_t)((wm * 64 + mt * 16 + a_row_l) * 128 +
                                           (ks * 2 + a_c16_l) * 16);
                uint32_t so = swz(boff);
                ldsm_x4(ahi[mt][0], ahi[mt][1], ahi[mt][2], ahi[mt][3], sAhi + so);
                ldsm_x4(alo[mt][0], alo[mt][1], alo[mt][2], alo[mt][3], sAlo + so);
            }
            #pragma unroll
            for (int nt = 0; nt < 4; nt++) {
                uint32_t boff = (uint32_t)((wn * 32 + nt * 8 + b_row_l) * 128 +
                                           (ks * 2 + b_c16_l) * 16);
                uint32_t so = swz(boff);
                ldsm_x2(bhi[nt][0], bhi[nt][1], sBhi + so);
                ldsm_x2(blo[nt][0], blo[nt][1], sBlo + so);
            }
            #pragma unroll
            for (int mt = 0; mt < 4; mt++)
                #pragma unroll
                for (int nt = 0; nt < 4; nt++) {
                    mma16816bf(acc[mt][nt], ahi[mt], bhi[nt]);
                    mma16816bf(acc[mt][nt], ahi[mt], blo[nt]);
                    mma16816bf(acc[mt][nt], alo[mt], bhi[nt]);
                }
        }
        __syncthreads();
    }

    const int r_base = m0 + wm * 64 + (lane >> 2);
    const int c_base = n0 + wn * 32 + (lane & 3) * 2;
    #pragma unroll
    for (int mt = 0; mt < 4; mt++) {
        #pragma unroll
        for (int nt = 0; nt < 4; nt++) {
            int col = c_base + nt * 8;
            float bx = bias[col], by = bias[col + 1];
            int r0 = r_base + mt * 16;
            float2 v0 = {acc[mt][nt][0] + bx, acc[mt][nt][1] + by};
            float2 v1 = {acc[mt][nt][2] + bx, acc[mt][nt][3] + by};
            *(float2*)(C + (size_t)r0 * N + col) = v0;
            *(float2*)(C + (size_t)(r0 + 8) * N + col) = v1;
        }
    }
}

// ---------------------------------------------------------------------------
// RoPE + split-fp16 scatter for Q (scaled) and K: [v][h][p][d]
// ---------------------------------------------------------------------------
__global__ __launch_bounds__(256) void rope_scatter(
    const float* __restrict__ qkv, const float* __restrict__ rope)
{
    int idx = blockIdx.x * 256 + threadIdx.x;
    if (idx >= VB * PP * HH * 40) return;
    int d = idx % 40;
    int h = (idx / 40) % HH;
    int p = (idx / (40 * HH)) % PP;
    int v = idx / (40 * HH * PP);

    size_t row = (size_t)v * PP + p;
    const float* qr = qkv + row * N_QKV + h * HD;
    const float* kr = qr + DD;
    const float* rp = rope + row * (2 * HD);

    float c0 = rp[d],      c1 = rp[d + 40];
    float s0 = rp[HD + d], s1 = rp[HD + d + 40];
    float q0 = qr[d], q1 = qr[d + 40];
    float k0 = kr[d], k1 = kr[d + 40];

    float qa = (q0 * c0 - q1 * s0) * QK_SCALE;
    float qb = (q1 * c1 + q0 * s1) * QK_SCALE;
    float ka = k0 * c0 - k1 * s0;
    float kb = k1 * c1 + k0 * s1;

    size_t ob = (((size_t)v * HH + h) * PP + p) * HD;
    __half hqa = __float2half_rn(qa);
    __half hqb = __float2half_rn(qb);
    __half hka = __float2half_rn(ka);
    __half hkb = __float2half_rn(kb);
    g_qhi2[ob + d]      = hqa;
    g_qhi2[ob + d + 40] = hqb;
    g_qlo2[ob + d]      = __float2half_rn(qa - __half2float(hqa));
    g_qlo2[ob + d + 40] = __float2half_rn(qb - __half2float(hqb));
    g_khi2[ob + d]      = hka;
    g_khi2[ob + d + 40] = hkb;
    g_klo2[ob + d]      = __float2half_rn(ka - __half2float(hka));
    g_klo2[ob + d + 40] = __float2half_rn(kb - __half2float(hkb));
}

// ---------------------------------------------------------------------------
// V transpose: g_qkv V-part [v][p][h*80+d] -> g_vt [v][h][d][p] fp16
// ---------------------------------------------------------------------------
__global__ __launch_bounds__(256) void v_transpose(const float* __restrict__ qkv)
{
    __shared__ float t[32][33];
    int vh = blockIdx.z;
    int v = vh >> 4, h = vh & 15;
    int p0 = blockIdx.x * 32;
    int d0 = blockIdx.y * 32;
    int tx = threadIdx.x & 31, ty = threadIdx.x >> 5;
    #pragma unroll
    for (int r = ty; r < 32; r += 8) {
        int d = d0 + tx;
        if (d < HD)
            t[r][tx] = qkv[((size_t)v * PP + p0 + r) * N_QKV + 2 * DD + h * HD + d];
    }
    __syncthreads();
    #pragma unroll
    for (int r = ty; r < 32; r += 8) {
        int d = d0 + r;
        if (d < HD)
            g_vt[((size_t)vh * HD + d) * PP + p0 + tx] = __float2half_rn(t[tx][r]);
    }
}

// ---------------------------------------------------------------------------
// Tensor-core flash attention.
// CTA = 128 q-rows x one (v,h). 8 warps, each 16 q-rows.
// QK^T: fp16 split (3 products). PV: plain fp16 (1 product).
// Smem (halves): Qhi[128][88] Qlo[128][88] | Khi[2][64][88] Klo[2][64][88] | Vt[2][80][72]
// ---------------------------------------------------------------------------
#define SQ 88
#define SV 72
#define ATTN_SMEM 113152

__global__ __launch_bounds__(256) void attn_mma(const int* __restrict__ valid_lens)
{
    extern __shared__ char smem[];
    uint32_t sb = smem_u32(smem);
    const int tid = threadIdx.x;
    const int lane = tid & 31;
    const int wq = tid >> 5;
    const int q0 = blockIdx.x * 128;
    const int h = blockIdx.y;
    const int v = blockIdx.z;
    int L = valid_lens[v];
    if (L < 1) L = 1;

    const size_t hb = ((size_t)(v * HH + h)) * PP * HD;
    const __half* qhi = g_qhi2 + hb + (size_t)q0 * HD;
    const __half* qlo = g_qlo2 + hb + (size_t)q0 * HD;
    const __half* khi = g_khi2 + hb;
    const __half* klo = g_klo2 + hb;
    const __half* vtp = g_vt + hb;   // [80][2048]

    const uint32_t bQHI = sb;
    const uint32_t bQLO = sb + 22528u;
    const uint32_t bKHI = sb + 45056u;
    const uint32_t bKLO = sb + 67584u;
    const uint32_t bVT  = sb + 90112u;

    // Q tiles (resident)
    for (int i = tid; i < 1280; i += 256) {
        int r = i / 10, g = i % 10;
        uint32_t off = (uint32_t)(r * SQ + g * 8) * 2;
        CP_ASYNC16(bQHI + off, qhi + (size_t)r * HD + g * 8);
        CP_ASYNC16(bQLO + off, qlo + (size_t)r * HD + g * 8);
    }
    // first K/V tile into buffer 0
    {
        for (int i = tid; i < 640; i += 256) {
            int r = i / 10, g = i % 10;
            uint32_t off = (uint32_t)(r * SQ + g * 8) * 2;
            CP_ASYNC16(bKHI + off, khi + (size_t)r * HD + g * 8);
            CP_ASYNC16(bKLO + off, klo + (size_t)r * HD + g * 8);
        }
        for (int i = tid; i < 640; i += 256) {
            int d = i / 8, g = i % 8;
            CP_ASYNC16(bVT + (uint32_t)(d * SV + g * 8) * 2, vtp + (size_t)d * PP + g * 8);
        }
    }
    CP_COMMIT();

    float m_lo = -1e30f, m_hi = -1e30f, l_lo = 0.f, l_hi = 0.f;
    float o[10][4];
    #pragma unroll
    for (int i = 0; i < 10; i++)
        #pragma unroll
        for (int j = 0; j < 4; j++) o[i][j] = 0.f;

    const int a_row = wq * 16 + (lane & 7) + ((lane >> 3) & 1) * 8;
    const int a_c16 = (lane >> 4);
    const int b_row = (lane & 7);
    const int b_c16 = (lane >> 3) & 1;
    const int gc = lane & 3;

    const int nkt = (L + 63) >> 6;
    for (int kt = 0; kt < nkt; kt++) {
        const int b = kt & 1;
        if (kt + 1 < nkt) {
            const int kn = (kt + 1) * 64;
            const uint32_t kh = bKHI + (uint32_t)(b ^ 1) * 11264u;
            const uint32_t kl = bKLO + (uint32_t)(b ^ 1) * 11264u;
            const uint32_t vb = bVT + (uint32_t)(b ^ 1) * 11520u;
            for (int i = tid; i < 640; i += 256) {
                int r = i / 10, g = i % 10;
                uint32_t off = (uint32_t)(r * SQ + g * 8) * 2;
                CP_ASYNC16(kh + off, khi + (size_t)(kn + r) * HD + g * 8);
                CP_ASYNC16(kl + off, klo + (size_t)(kn + r) * HD + g * 8);
            }
            for (int i = tid; i < 640; i += 256) {
                int d = i / 8, g = i % 8;
                CP_ASYNC16(vb + (uint32_t)(d * SV + g * 8) * 2,
                           vtp + (size_t)d * PP + kn + g * 8);
            }
            CP_COMMIT();
            CP_WAIT(1);
        } else {
            CP_WAIT(0);
        }
        __syncthreads();

        const uint32_t khb = bKHI + (uint32_t)b * 11264u;
        const uint32_t klb = bKLO + (uint32_t)b * 11264u;
        const uint32_t vtb = bVT + (uint32_t)b * 11520u;

        // S = Q K^T (split fp16, 3 products)
        float s[8][4];
        #pragma unroll
        for (int nt = 0; nt < 8; nt++)
            #pragma unroll
            for (int j = 0; j < 4; j++) s[nt][j] = 0.f;

        #pragma unroll
        for (int kc = 0; kc < 5; kc++) {
            uint32_t qh[4], ql[4];
            uint32_t qoff = (uint32_t)(a_row * SQ + kc * 16 + a_c16 * 8) * 2;
            ldsm_x4(qh[0], qh[1], qh[2], qh[3], bQHI + qoff);
            ldsm_x4(ql[0], ql[1], ql[2], ql[3], bQLO + qoff);
            #pragma unroll
            for (int nt = 0; nt < 8; nt++) {
                uint32_t koff = (uint32_t)((nt * 8 + b_row) * SQ + kc * 16 + b_c16 * 8) * 2;
                uint32_t kh[2], kl[2];
                ldsm_x2(kh[0], kh[1], khb + koff);
                ldsm_x2(kl[0], kl[1], klb + koff);
                mma16816h(s[nt], qh, kh);
                mma16816h(s[nt], qh, kl);
                mma16816h(s[nt], ql, kh);
            }
        }

        // mask (final tile only)
        const int k0 = kt * 64;
        if (k0 + 64 > L) {
            #pragma unroll
            for (int nt = 0; nt < 8; nt++) {
                int kb0 = k0 + nt * 8 + gc * 2;
                if (kb0 >= L)     { s[nt][0] = -1e30f; s[nt][2] = -1e30f; }
                if (kb0 + 1 >= L) { s[nt][1] = -1e30f; s[nt][3] = -1e30f; }
            }
        }

        // online softmax (rows: lo = gr, hi = gr+8)
        float mt_lo = -1e30f, mt_hi = -1e30f;
        #pragma unroll
        for (int nt = 0; nt < 8; nt++) {
            mt_lo = fmaxf(mt_lo, fmaxf(s[nt][0], s[nt][1]));
            mt_hi = fmaxf(mt_hi, fmaxf(s[nt][2], s[nt][3]));
        }
        mt_lo = fmaxf(mt_lo, __shfl_xor_sync(0xffffffffu, mt_lo, 1));
        mt_lo = fmaxf(mt_lo, __shfl_xor_sync(0xffffffffu, mt_lo, 2));
        mt_hi = fmaxf(mt_hi, __shfl_xor_sync(0xffffffffu, mt_hi, 1));
        mt_hi = fmaxf(mt_hi, __shfl_xor_sync(0xffffffffu, mt_hi, 2));

        float mn_lo = fmaxf(m_lo, mt_lo), mn_hi = fmaxf(m_hi, mt_hi);
        float al = __expf(m_lo - mn_lo), ah = __expf(m_hi - mn_hi);
        m_lo = mn_lo; m_hi = mn_hi;

        float sum_lo = 0.f, sum_hi = 0.f;
        #pragma unroll
        for (int nt = 0; nt < 8; nt++) {
            s[nt][0] = __expf(s[nt][0] - mn_lo);
            s[nt][1] = __expf(s[nt][1] - mn_lo);
            s[nt][2] = __expf(s[nt][2] - mn_hi);
            s[nt][3] = __expf(s[nt][3] - mn_hi);
            sum_lo += s[nt][0] + s[nt][1];
            sum_hi += s[nt][2] + s[nt][3];
        }
        sum_lo += __shfl_xor_sync(0xffffffffu, sum_lo, 1);
        sum_lo += __shfl_xor_sync(0xffffffffu, sum_lo, 2);
        sum_hi += __shfl_xor_sync(0xffffffffu, sum_hi, 1);
        sum_hi += __shfl_xor_sync(0xffffffffu, sum_hi, 2);
        l_lo = l_lo * al + sum_lo;
        l_hi = l_hi * ah + sum_hi;

        #pragma unroll
        for (int nt = 0; nt < 10; nt++) {
            o[nt][0] *= al; o[nt][1] *= al;
            o[nt][2] *= ah; o[nt][3] *= ah;
        }

        // pack P into A-fragments (fp16)
        uint32_t pa[4][4];
        #pragma unroll
        for (int kc = 0; kc < 4; kc++) {
            __half2 t0 = __floats2half2_rn(s[2 * kc][0], s[2 * kc][1]);
            __half2 t1 = __floats2half2_rn(s[2 * kc][2], s[2 * kc][3]);
            __half2 t2 = __floats2half2_rn(s[2 * kc + 1][0], s[2 * kc + 1][1]);
            __half2 t3 = __floats2half2_rn(s[2 * kc + 1][2], s[2 * kc + 1][3]);
            pa[kc][0] = *(uint32_t*)&t0;
            pa[kc][1] = *(uint32_t*)&t1;
            pa[kc][2] = *(uint32_t*)&t2;
            pa[kc][3] = *(uint32_t*)&t3;
        }

        // O += P @ V  (V^T fragments)
        #pragma unroll
        for (int nt = 0; nt < 10; nt++) {
            #pragma unroll
            for (int kc = 0; kc < 4; kc++) {
                uint32_t voff = (uint32_t)((nt * 8 + b_row) * SV + kc * 16 + b_c16 * 8) * 2;
                uint32_t vv[2];
                ldsm_x2(vv[0], vv[1], vtb + voff);
                mma16816h(o[nt], pa[kc], vv);
            }
        }
        __syncthreads();
    }

    // epilogue
    float inv_lo = 1.f / l_lo, inv_hi = 1.f / l_hi;
    int row_lo = q0 + wq * 16 + (lane >> 2);
    #pragma unroll
    for (int nt = 0; nt < 10; nt++) {
        int col = h * HD + nt * 8 + gc * 2;
        float2 v0 = {o[nt][0] * inv_lo, o[nt][1] * inv_lo};
        float2 v1 = {o[nt][2] * inv_hi, o[nt][3] * inv_hi};
        *(float2*)(g_ao + ((size_t)v * PP + row_lo) * DD + col) = v0;
        *(float2*)(g_ao + ((size_t)v * PP + row_lo + 8) * DD + col) = v1;
    }
}

// ---------------------------------------------------------------------------
// Launch
// ---------------------------------------------------------------------------
extern "C" void kernel_launch(void* const* d_in, const int* in_sizes, int n_in,
                              void* d_out, int out_size)
{
    const float* hs    = (const float*)d_in[0];
    const float* rope  = (const float*)d_in[1];
    const int*   vlens = (const int*)d_in[2];
    const float* wqkv  = (const float*)d_in[3];
    const float* bqkv  = (const float*)d_in[4];
    const float* wproj = (const float*)d_in[5];
    const float* bproj = (const float*)d_in[6];
    float* out = (float*)d_out;

    float *p_qkv, *p_ao;
    __nv_bfloat16 *p_ahi, *p_alo, *p_bhi, *p_blo;
    cudaGetSymbolAddress((void**)&p_qkv, g_qkv);
    cudaGetSymbolAddress((void**)&p_ao,  g_ao);
    cudaGetSymbolAddress((void**)&p_ahi, g_ahi);
    cudaGetSymbolAddress((void**)&p_alo, g_alo);
    cudaGetSymbolAddress((void**)&p_bhi, g_bhi);
    cudaGetSymbolAddress((void**)&p_blo, g_blo);

    cudaFuncSetAttribute(gemm_mma_bf16x3,
                         cudaFuncAttributeMaxDynamicSharedMemorySize, GEMM_SMEM);
    cudaFuncSetAttribute(attn_mma,
                         cudaFuncAttributeMaxDynamicSharedMemorySize, ATTN_SMEM);

    // 1) Split hidden states, transpose+split W_qkv
    {
        int n = M_ROWS * DD;
        split_kernel<<<(n / 4 + 255) / 256, 256>>>(hs, p_ahi, p_alo, n);
        transpose_split<<<dim3(N_QKV / 32, DD / 32), 256>>>(wqkv, p_bhi, p_blo, DD, N_QKV);
    }

    // 2) QKV GEMM
    gemm_mma_bf16x3<<<dim3(N_QKV / GTN, M_ROWS / GTM), 256, GEMM_SMEM>>>(
        p_ahi, p_alo, p_bhi, p_blo, bqkv, p_qkv, DD, N_QKV);

    // 3) RoPE (split fp16 Q/K) + V transpose (fp16)
    {
        int total = VB * PP * HH * 40;
        rope_scatter<<<(total + 255) / 256, 256>>>(p_qkv, rope);
        v_transpose<<<dim3(PP / 32, 3, VB * HH), 256>>>(p_qkv);
    }

    // 4) Tensor-core flash attention
    attn_mma<<<dim3(PP / 128, HH, VB), 256, ATTN_SMEM>>>(vlens);

    // 5) Split attention output, transpose+split W_proj
    {
        int n = M_ROWS * DD;
        split_kernel<<<(n / 4 + 255) / 256, 256>>>(p_ao, p_ahi, p_alo, n);
        transpose_split<<<dim3(DD / 32, DD / 32), 256>>>(wproj, p_bhi, p_blo, DD, DD);
    }

    // 6) Output projection
    gemm_mma_bf16x3<<<dim3(DD / GTN, M_ROWS / GTM), 256, GEMM_SMEM>>>(
        p_ahi, p_alo, p_bhi, p_blo, bproj, out, DD, DD);
}